// round 3
// baseline (speedup 1.0000x reference)
#include <cuda_runtime.h>
#include <mma.h>
#include <math.h>
using namespace nvcuda;

#define Bb 4
#define Ss 2048
#define Dd 512
#define Hh 8

// ---------------- scratch ---------------------------------------------------
__device__ float g_xn [Bb*Ss*Dd];
__device__ float g_q  [Bb*Ss*Dd];
__device__ float g_k  [Bb*Ss*Dd];
__device__ float g_v  [Bb*Ss*Dd];
__device__ float g_ctx[Bb*Ss*Dd];
__device__ float g_pe [Ss*Dd];
__device__ float g_pos[Ss*Dd];
__device__ float g_ps [(size_t)Bb*Hh*Ss*Ss];   // 512 MB raw position scores

__device__ __forceinline__ float f2t(float x) {
    unsigned r; asm("cvt.rna.tf32.f32 %0, %1;" : "=r"(r) : "f"(x));
    return __uint_as_float(r);
}

// ---------------- sinusoidal positional encoding ---------------------------
__global__ void pe_kernel(float* __restrict__ pe) {
    int idx = blockIdx.x * blockDim.x + threadIdx.x;
    int s = idx >> 8;
    int i = idx & 255;
    float div = expf((2.0f * (float)i) * (-9.210340371976184f / 512.0f));
    float a = (float)s * div;
    pe[s * Dd + 2 * i]     = sinf(a);
    pe[s * Dd + 2 * i + 1] = cosf(a);
}

// ---------------- layernorm -------------------------------------------------
__global__ void ln_kernel(const float* __restrict__ x,
                          const float* __restrict__ gamma,
                          const float* __restrict__ beta,
                          float* __restrict__ out) {
    int row = blockIdx.x;
    const float2* xr = (const float2*)(x + (size_t)row * Dd);
    int t = threadIdx.x;
    float2 v = xr[t];
    float s1 = v.x + v.y;
    float s2 = v.x * v.x + v.y * v.y;
    #pragma unroll
    for (int o = 16; o; o >>= 1) {
        s1 += __shfl_xor_sync(0xffffffffu, s1, o);
        s2 += __shfl_xor_sync(0xffffffffu, s2, o);
    }
    __shared__ float r1[8], r2[8];
    if ((t & 31) == 0) { r1[t >> 5] = s1; r2[t >> 5] = s2; }
    __syncthreads();
    float S1 = 0.f, S2 = 0.f;
    #pragma unroll
    for (int i = 0; i < 8; i++) { S1 += r1[i]; S2 += r2[i]; }
    float mean = S1 * (1.0f / 512.0f);
    float var  = S2 * (1.0f / 512.0f) - mean * mean;
    float rstd = rsqrtf(var + 1e-5f);
    float2 g  = ((const float2*)gamma)[t];
    float2 bt = ((const float2*)beta)[t];
    float2 o2;
    o2.x = (v.x - mean) * rstd * g.x + bt.x;
    o2.y = (v.y - mean) * rstd * g.y + bt.y;
    ((float2*)(out + (size_t)row * Dd))[t] = o2;
}

// ---------------- TF32 wmma: C = A @ W^T + bias -----------------------------
__global__ void __launch_bounds__(256) gemm_nt_wmma(
        const float* __restrict__ A, const float* __restrict__ W,
        const float* __restrict__ bias, float* __restrict__ C,
        int M, int N, int K) {
    __shared__ float sm[128 * 68];
    float* As = sm;                             // [128][36]
    float* Bs = sm + 128 * 36;                  // [64][36]
    const int t = threadIdx.x;
    const int warp = t >> 5;
    const int wm = warp & 3, wn = warp >> 2;
    const int m0 = blockIdx.y * 128, n0 = blockIdx.x * 64;

    wmma::fragment<wmma::accumulator, 16, 16, 8, float> acc[2][2];
    #pragma unroll
    for (int i = 0; i < 2; i++)
        #pragma unroll
        for (int j = 0; j < 2; j++) wmma::fill_fragment(acc[i][j], 0.0f);

    for (int k0 = 0; k0 < K; k0 += 32) {
        #pragma unroll
        for (int i = 0; i < 4; i++) {
            int idx = i * 256 + t, row = idx >> 3, c = (idx & 7) * 4;
            float4 v = *(const float4*)(A + (size_t)(m0 + row) * K + k0 + c);
            float* d = &As[row * 36 + c];
            d[0] = f2t(v.x); d[1] = f2t(v.y); d[2] = f2t(v.z); d[3] = f2t(v.w);
        }
        #pragma unroll
        for (int i = 0; i < 2; i++) {
            int idx = i * 256 + t, row = idx >> 3, c = (idx & 7) * 4;
            float4 v = *(const float4*)(W + (size_t)(n0 + row) * K + k0 + c);
            float* d = &Bs[row * 36 + c];
            d[0] = f2t(v.x); d[1] = f2t(v.y); d[2] = f2t(v.z); d[3] = f2t(v.w);
        }
        __syncthreads();
        #pragma unroll
        for (int kk = 0; kk < 4; kk++) {
            wmma::fragment<wmma::matrix_a, 16, 16, 8, wmma::precision::tf32, wmma::row_major> a[2];
            wmma::fragment<wmma::matrix_b, 16, 16, 8, wmma::precision::tf32, wmma::col_major> b[2];
            wmma::load_matrix_sync(a[0], &As[(wm * 32) * 36 + kk * 8], 36);
            wmma::load_matrix_sync(a[1], &As[(wm * 32 + 16) * 36 + kk * 8], 36);
            wmma::load_matrix_sync(b[0], &Bs[(wn * 32) * 36 + kk * 8], 36);
            wmma::load_matrix_sync(b[1], &Bs[(wn * 32 + 16) * 36 + kk * 8], 36);
            #pragma unroll
            for (int i = 0; i < 2; i++)
                #pragma unroll
                for (int j = 0; j < 2; j++)
                    wmma::mma_sync(acc[i][j], a[i], b[j], acc[i][j]);
        }
        __syncthreads();
    }
    #pragma unroll
    for (int i = 0; i < 2; i++)
        #pragma unroll
        for (int j = 0; j < 2; j++)
            wmma::store_matrix_sync(&sm[(wm * 32 + i * 16) * 68 + wn * 32 + j * 16],
                                    acc[i][j], 68, wmma::mem_row_major);
    __syncthreads();
    #pragma unroll
    for (int i = 0; i < 8; i++) {
        int idx = i * 256 + t, row = idx >> 4, c = (idx & 15) * 4;
        float4 o;
        float b0 = 0.f, b1 = 0.f, b2 = 0.f, b3 = 0.f;
        if (bias) { b0 = bias[n0+c]; b1 = bias[n0+c+1]; b2 = bias[n0+c+2]; b3 = bias[n0+c+3]; }
        o.x = sm[row * 68 + c]     + b0;
        o.y = sm[row * 68 + c + 1] + b1;
        o.z = sm[row * 68 + c + 2] + b2;
        o.w = sm[row * 68 + c + 3] + b3;
        *(float4*)(C + (size_t)(m0 + row) * N + n0 + c) = o;
    }
}

// ---------------- TF32 wmma: PS[bh,s,t] = (q_s + v_bias) . pos_t ------------
__global__ void __launch_bounds__(256) qk_wmma(
        const float* __restrict__ q, const float* __restrict__ X,
        const float* __restrict__ hbias, float* __restrict__ out) {
    __shared__ float sm[2 * 128 * 36];
    float* Qs = sm;
    float* Ks = sm + 128 * 36;
    const int t = threadIdx.x;
    const int warp = t >> 5;
    const int wm = warp & 1, wn = warp >> 1;
    const int bh = blockIdx.z, b = bh >> 3, h = bh & 7;
    const int s0 = blockIdx.y * 128, t0 = blockIdx.x * 128;

    wmma::fragment<wmma::accumulator, 16, 16, 8, float> acc[4][2];
    #pragma unroll
    for (int i = 0; i < 4; i++)
        #pragma unroll
        for (int j = 0; j < 2; j++) wmma::fill_fragment(acc[i][j], 0.0f);

    #pragma unroll
    for (int kc = 0; kc < 2; kc++) {
        const int koff = h * 64 + kc * 32;
        #pragma unroll
        for (int i = 0; i < 4; i++) {
            int idx = i * 256 + t, row = idx >> 3, c = (idx & 7) * 4;
            float4 v = *(const float4*)(q + (size_t)(b * Ss + s0 + row) * Dd + koff + c);
            const float* bb = &hbias[h * 64 + kc * 32 + c];
            float* d = &Qs[row * 36 + c];
            d[0] = f2t(v.x + bb[0]); d[1] = f2t(v.y + bb[1]);
            d[2] = f2t(v.z + bb[2]); d[3] = f2t(v.w + bb[3]);
        }
        #pragma unroll
        for (int i = 0; i < 4; i++) {
            int idx = i * 256 + t, row = idx >> 3, c = (idx & 7) * 4;
            float4 v = *(const float4*)(X + (size_t)(t0 + row) * Dd + koff + c);
            float* d = &Ks[row * 36 + c];
            d[0] = f2t(v.x); d[1] = f2t(v.y); d[2] = f2t(v.z); d[3] = f2t(v.w);
        }
        __syncthreads();
        #pragma unroll
        for (int kk = 0; kk < 4; kk++) {
            wmma::fragment<wmma::matrix_a, 16, 16, 8, wmma::precision::tf32, wmma::row_major> a[4];
            wmma::fragment<wmma::matrix_b, 16, 16, 8, wmma::precision::tf32, wmma::col_major> bf[2];
            #pragma unroll
            for (int i = 0; i < 4; i++)
                wmma::load_matrix_sync(a[i], &Qs[(wm * 64 + i * 16) * 36 + kk * 8], 36);
            #pragma unroll
            for (int j = 0; j < 2; j++)
                wmma::load_matrix_sync(bf[j], &Ks[(wn * 32 + j * 16) * 36 + kk * 8], 36);
            #pragma unroll
            for (int i = 0; i < 4; i++)
                #pragma unroll
                for (int j = 0; j < 2; j++)
                    wmma::mma_sync(acc[i][j], a[i], bf[j], acc[i][j]);
        }
        __syncthreads();
    }
    #pragma unroll
    for (int i = 0; i < 4; i++)
        #pragma unroll
        for (int j = 0; j < 2; j++)
            wmma::store_matrix_sync(
                out + ((size_t)bh * Ss + s0 + wm * 64 + i * 16) * Ss + t0 + wn * 32 + j * 16,
                acc[i][j], Ss, wmma::mem_row_major);
}

// ---------------- fused flash attention -------------------------------------
// Per (bh, 64-row s-tile): stream 64-col t-tiles.
// score = ((Q+u)K^T + shift(PS)) * scale ; online softmax ; O += P @ V.
__global__ void __launch_bounds__(256) flash_kernel(
        const float* __restrict__ q, const float* __restrict__ k,
        const float* __restrict__ v, const float* __restrict__ ps,
        const float* __restrict__ ubias, float* __restrict__ ctx) {
    extern __shared__ float sm[];
    float* Qs = sm;                 // [64][68] Q+u (tf32)
    float* Ks = Qs + 64 * 68;       // [64][68] K tile (tf32); reused for PV delta
    float* Vs = Ks + 64 * 68;       // [64][68] V tile (tf32)
    float* Sc = Vs + 64 * 68;       // [64][68] score / P tile
    float* mrow = Sc + 64 * 68;     // [64]
    float* lrow = mrow + 64;        // [64]
    float* frow = lrow + 64;        // [64]

    const int t = threadIdx.x;
    const int warp = t >> 5;
    const int wm = warp & 1, wn = warp >> 1;   // 2x4 warps: 32(s) x 16(cols)
    const int bh = blockIdx.y, b = bh >> 3, h = bh & 7;
    const int s0 = blockIdx.x * 64;
    const int r = t >> 2, cq = t & 3;          // thread -> row r, col phase cq
    const int s = s0 + r;                      // this thread's global row
    const float* p0 = ps + ((size_t)bh * Ss + s) * Ss;   // PS row s
    const float* p1 = p0 + Ss;                           // PS row s+1

    // load Q tile + u_bias
    #pragma unroll
    for (int i = 0; i < 4; i++) {
        int idx = i * 256 + t, row = idx >> 4, c = (idx & 15) * 4;
        float4 qv = *(const float4*)(q + (size_t)(b * Ss + s0 + row) * Dd + h * 64 + c);
        const float* ub = ubias + h * 64 + c;
        float* d = &Qs[row * 68 + c];
        d[0] = f2t(qv.x + ub[0]); d[1] = f2t(qv.y + ub[1]);
        d[2] = f2t(qv.z + ub[2]); d[3] = f2t(qv.w + ub[3]);
    }
    if (t < 64) { mrow[t] = -1e30f; lrow[t] = 0.0f; }
    float O[16];
    #pragma unroll
    for (int j = 0; j < 16; j++) O[j] = 0.0f;
    __syncthreads();

    const float scale = 0.04419417382415922f;   // 1/sqrt(512)

    for (int t0 = 0; t0 < Ss; t0 += 64) {
        // load K, V tiles (tf32)
        #pragma unroll
        for (int i = 0; i < 4; i++) {
            int idx = i * 256 + t, row = idx >> 4, c = (idx & 15) * 4;
            float4 kv = *(const float4*)(k + (size_t)(b * Ss + t0 + row) * Dd + h * 64 + c);
            float* d = &Ks[row * 68 + c];
            d[0] = f2t(kv.x); d[1] = f2t(kv.y); d[2] = f2t(kv.z); d[3] = f2t(kv.w);
            float4 vv = *(const float4*)(v + (size_t)(b * Ss + t0 + row) * Dd + h * 64 + c);
            float* e = &Vs[row * 68 + c];
            e[0] = f2t(vv.x); e[1] = f2t(vv.y); e[2] = f2t(vv.z); e[3] = f2t(vv.w);
        }
        __syncthreads();

        // content score tile: (Q+u) @ K^T
        {
            wmma::fragment<wmma::accumulator, 16, 16, 8, float> acc[2];
            #pragma unroll
            for (int i = 0; i < 2; i++) wmma::fill_fragment(acc[i], 0.0f);
            #pragma unroll
            for (int kk = 0; kk < 8; kk++) {
                wmma::fragment<wmma::matrix_a, 16, 16, 8, wmma::precision::tf32, wmma::row_major> a[2];
                wmma::fragment<wmma::matrix_b, 16, 16, 8, wmma::precision::tf32, wmma::col_major> bf;
                #pragma unroll
                for (int i = 0; i < 2; i++)
                    wmma::load_matrix_sync(a[i], &Qs[(wm * 32 + i * 16) * 68 + kk * 8], 68);
                wmma::load_matrix_sync(bf, &Ks[(wn * 16) * 68 + kk * 8], 68);
                #pragma unroll
                for (int i = 0; i < 2; i++)
                    wmma::mma_sync(acc[i], a[i], bf, acc[i]);
            }
            #pragma unroll
            for (int i = 0; i < 2; i++)
                wmma::store_matrix_sync(&Sc[(wm * 32 + i * 16) * 68 + wn * 16],
                                        acc[i], 68, wmma::mem_row_major);
        }
        __syncthreads();

        // fused rel_shift + scale + online softmax (each thread: row r, cols cq+4j)
        {
            float vals[16];
            float tmax = -1e30f;
            #pragma unroll
            for (int j = 0; j < 16; j++) {
                int tt = t0 + cq + 4 * j;
                float p;
                if (tt <= s)          p = p0[Ss - 1 - s + tt];
                else if (tt == s + 1) p = 0.0f;
                else                  p = p1[tt - s - 2];
                float val = (Sc[r * 68 + cq + 4 * j] + p) * scale;
                vals[j] = val;
                tmax = fmaxf(tmax, val);
            }
            tmax = fmaxf(tmax, __shfl_xor_sync(0xffffffffu, tmax, 1));
            tmax = fmaxf(tmax, __shfl_xor_sync(0xffffffffu, tmax, 2));
            float mold = mrow[r];
            float mnew = fmaxf(mold, tmax);
            float sum = 0.0f;
            #pragma unroll
            for (int j = 0; j < 16; j++) {
                float e = __expf(vals[j] - mnew);
                sum += e;
                Sc[r * 68 + cq + 4 * j] = f2t(e);
            }
            sum += __shfl_xor_sync(0xffffffffu, sum, 1);
            sum += __shfl_xor_sync(0xffffffffu, sum, 2);
            float fac = __expf(mold - mnew);
            if (cq == 0) {
                mrow[r] = mnew;
                lrow[r] = lrow[r] * fac + sum;
                frow[r] = fac;
            }
        }
        __syncthreads();

        // delta = P @ V  (write into Ks buffer, K tile already consumed)
        {
            wmma::fragment<wmma::accumulator, 16, 16, 8, float> acc[2];
            #pragma unroll
            for (int i = 0; i < 2; i++) wmma::fill_fragment(acc[i], 0.0f);
            #pragma unroll
            for (int kk = 0; kk < 8; kk++) {
                wmma::fragment<wmma::matrix_a, 16, 16, 8, wmma::precision::tf32, wmma::row_major> a[2];
                wmma::fragment<wmma::matrix_b, 16, 16, 8, wmma::precision::tf32, wmma::row_major> bf;
                #pragma unroll
                for (int i = 0; i < 2; i++)
                    wmma::load_matrix_sync(a[i], &Sc[(wm * 32 + i * 16) * 68 + kk * 8], 68);
                wmma::load_matrix_sync(bf, &Vs[(kk * 8) * 68 + wn * 16], 68);
                #pragma unroll
                for (int i = 0; i < 2; i++)
                    wmma::mma_sync(acc[i], a[i], bf, acc[i]);
            }
            #pragma unroll
            for (int i = 0; i < 2; i++)
                wmma::store_matrix_sync(&Ks[(wm * 32 + i * 16) * 68 + wn * 16],
                                        acc[i], 68, wmma::mem_row_major);
        }
        __syncthreads();

        // O = O * factor + delta
        {
            float fr = frow[r];
            #pragma unroll
            for (int j = 0; j < 16; j++)
                O[j] = O[j] * fr + Ks[r * 68 + cq + 4 * j];
        }
        __syncthreads();   // protect Ks/Vs before next tile's loads
    }

    float inv = 1.0f / lrow[r];
    #pragma unroll
    for (int j = 0; j < 16; j++)
        ctx[(size_t)(b * Ss + s0 + r) * Dd + h * 64 + cq + 4 * j] = O[j] * inv;
}

// ---------------- launch -----------------------------------------------------
extern "C" void kernel_launch(void* const* d_in, const int* in_sizes, int n_in,
                              void* d_out, int out_size) {
    const float* inputs = (const float*)d_in[0];
    const float* gamma  = (const float*)d_in[1];
    const float* beta   = (const float*)d_in[2];
    const float* Wq     = (const float*)d_in[3];
    const float* bq     = (const float*)d_in[4];
    const float* Wk     = (const float*)d_in[5];
    const float* bk     = (const float*)d_in[6];
    const float* Wv     = (const float*)d_in[7];
    const float* bv     = (const float*)d_in[8];
    const float* Wpos   = (const float*)d_in[9];
    const float* ub     = (const float*)d_in[10];
    const float* vb     = (const float*)d_in[11];
    const float* Wo     = (const float*)d_in[12];
    const float* bo     = (const float*)d_in[13];
    float* out = (float*)d_out;

    float *xn, *q, *k, *v, *ctx, *pe, *pos, *ps;
    cudaGetSymbolAddress((void**)&xn,  g_xn);
    cudaGetSymbolAddress((void**)&q,   g_q);
    cudaGetSymbolAddress((void**)&k,   g_k);
    cudaGetSymbolAddress((void**)&v,   g_v);
    cudaGetSymbolAddress((void**)&ctx, g_ctx);
    cudaGetSymbolAddress((void**)&pe,  g_pe);
    cudaGetSymbolAddress((void**)&pos, g_pos);
    cudaGetSymbolAddress((void**)&ps,  g_ps);

    static bool attr_set = false;
    if (!attr_set) {
        cudaFuncSetAttribute(flash_kernel,
                             cudaFuncAttributeMaxDynamicSharedMemorySize, 71000);
        attr_set = true;
    }

    pe_kernel<<<2048, 256>>>(pe);
    ln_kernel<<<Bb * Ss, 256>>>(inputs, gamma, beta, xn);

    gemm_nt_wmma<<<dim3(8, 64), 256>>>(xn, Wq, bq, q, 8192, 512, 512);
    gemm_nt_wmma<<<dim3(8, 64), 256>>>(xn, Wk, bk, k, 8192, 512, 512);
    gemm_nt_wmma<<<dim3(8, 64), 256>>>(xn, Wv, bv, v, 8192, 512, 512);
    gemm_nt_wmma<<<dim3(8, 16), 256>>>(pe, Wpos, nullptr, pos, 2048, 512, 512);

    qk_wmma<<<dim3(16, 16, 32), 256>>>(q, pos, vb, ps);       // raw PS

    size_t smem = (4 * 64 * 68 + 3 * 64) * sizeof(float);     // 70400 B
    flash_kernel<<<dim3(32, 32), 256, smem>>>(q, k, v, ps, ub, ctx);

    gemm_nt_wmma<<<dim3(8, 64), 256>>>(ctx, Wo, bo, out, 8192, 512, 512);
}